// round 12
// baseline (speedup 1.0000x reference)
#include <cuda_runtime.h>
#include <cuda_bf16.h>
#include <cstdint>

#define BATCH 2
#define SEQ   2048
#define DIMN  768
#define NH    12
#define HD    64

#define TQ 32
#define TK 32

#define KSTR 776           /* bf16 row stride: 1552B -> 16B aligned, conflict-free ldmatrix */
#define PST  18            /* fp32 exp-exchange row stride (floats); even -> float2-aligned */

// attn smem layout (bytes)
#define OFF_A   0                         /* K tile: hi, then lo            */
#define A_LO    49664                     /* 32*776*2                        */
#define OFF_B   99328                     /* V tile: hi, then lo             */
#define B_LO    49664
#define OFF_P   198656                    /* sP fp32 [NH][32][PST] = 27648   */
#define OFF_I   226304                    /* sInv fp32 [2][32][PST] = 4608   */
#define SMEM_TOTAL 230912

// split-bf16 operands
__device__ __align__(16) __nv_bfloat16 g_Xh[4096 * DIMN];
__device__ __align__(16) __nv_bfloat16 g_Xl[4096 * DIMN];
__device__ __align__(16) __nv_bfloat16 g_Wh[3 * DIMN * DIMN];
__device__ __align__(16) __nv_bfloat16 g_Wl[3 * DIMN * DIMN];

// split-bf16 Q/K/V (hi + lo)
__device__ __align__(16) __nv_bfloat16 g_Qh[BATCH * SEQ * DIMN];
__device__ __align__(16) __nv_bfloat16 g_Ql[BATCH * SEQ * DIMN];
__device__ __align__(16) __nv_bfloat16 g_Kh[BATCH * SEQ * DIMN];
__device__ __align__(16) __nv_bfloat16 g_Kl[BATCH * SEQ * DIMN];
__device__ __align__(16) __nv_bfloat16 g_Vh[BATCH * SEQ * DIMN];
__device__ __align__(16) __nv_bfloat16 g_Vl[BATCH * SEQ * DIMN];

// ---------------------------------------------------------------------------
// exp via MUFU (EX2); tensor cores own the math, MUFU pipe is idle.
__device__ __forceinline__ float fast_exp(float s) {
    float t = s * 1.4426950408889634f;
    float r;
    asm("ex2.approx.f32 %0, %1;" : "=f"(r) : "f"(t));
    return r;
}

__device__ __forceinline__ uint32_t smem_u32(const void* p) {
    return (uint32_t)__cvta_generic_to_shared(p);
}
__device__ __forceinline__ void ldm_x4(uint32_t r[4], uint32_t addr) {
    asm volatile("ldmatrix.sync.aligned.m8n8.x4.shared.b16 {%0,%1,%2,%3}, [%4];"
                 : "=r"(r[0]), "=r"(r[1]), "=r"(r[2]), "=r"(r[3]) : "r"(addr));
}
__device__ __forceinline__ void ldm_x4_t(uint32_t r[4], uint32_t addr) {
    asm volatile("ldmatrix.sync.aligned.m8n8.x4.trans.shared.b16 {%0,%1,%2,%3}, [%4];"
                 : "=r"(r[0]), "=r"(r[1]), "=r"(r[2]), "=r"(r[3]) : "r"(addr));
}
__device__ __forceinline__ void mma_bf16(float c[4], const uint32_t a[4],
                                         uint32_t b0, uint32_t b1) {
    asm volatile(
        "mma.sync.aligned.m16n8k16.row.col.f32.bf16.bf16.f32 "
        "{%0,%1,%2,%3}, {%4,%5,%6,%7}, {%8,%9}, {%0,%1,%2,%3};"
        : "+f"(c[0]), "+f"(c[1]), "+f"(c[2]), "+f"(c[3])
        : "r"(a[0]), "r"(a[1]), "r"(a[2]), "r"(a[3]), "r"(b0), "r"(b1));
}
__device__ __forceinline__ void cp16(uint32_t saddr, const void* gaddr) {
    asm volatile("cp.async.cg.shared.global [%0], [%1], 16;"
                 :: "r"(saddr), "l"(gaddr));
}
__device__ __forceinline__ void cp_commit() {
    asm volatile("cp.async.commit_group;" ::: "memory");
}
template <int N>
__device__ __forceinline__ void cp_wait() {
    asm volatile("cp.async.wait_group %0;" :: "n"(N) : "memory");
}
__device__ __forceinline__ uint32_t packbf(float a, float b) {
    __nv_bfloat162 h = __floats2bfloat162_rn(a, b);   // .x=a -> low half
    return *(uint32_t*)&h;
}
// named barrier over one 384-thread q-half (id 1 or 2)
__device__ __forceinline__ void bar_half(int id) {
    asm volatile("bar.sync %0, 384;" :: "r"(id) : "memory");
}

// ---------------------------------------------------------------------------
// Kernel 0: fp32 -> split bf16 (hi, lo). Destinations resolved in device code.
// ---------------------------------------------------------------------------
__global__ __launch_bounds__(256) void cvt_split(
    const float* __restrict__ src,
    int dst_sel, int off_elems, int n4)
{
    int i = blockIdx.x * 256 + threadIdx.x;
    if (i >= n4) return;
    __nv_bfloat16 *dh, *dl;
    if (dst_sel == 0) { dh = g_Xh; dl = g_Xl; }
    else              { dh = g_Wh; dl = g_Wl; }
    dh += off_elems;
    dl += off_elems;

    float4 v = ((const float4*)src)[i];
    __nv_bfloat162 h0 = __floats2bfloat162_rn(v.x, v.y);
    __nv_bfloat162 h1 = __floats2bfloat162_rn(v.z, v.w);
    __nv_bfloat162 l0 = __floats2bfloat162_rn(v.x - __bfloat162float(h0.x),
                                              v.y - __bfloat162float(h0.y));
    __nv_bfloat162 l1 = __floats2bfloat162_rn(v.z - __bfloat162float(h1.x),
                                              v.w - __bfloat162float(h1.y));
    ((__nv_bfloat162*)dh)[2 * i]     = h0;
    ((__nv_bfloat162*)dh)[2 * i + 1] = h1;
    ((__nv_bfloat162*)dl)[2 * i]     = l0;
    ((__nv_bfloat162*)dl)[2 * i + 1] = l1;
}

// ---------------------------------------------------------------------------
// Kernel 1: QKV projection on tensor cores, split-bf16 3-pass (unchanged).
// ---------------------------------------------------------------------------
#define Q_AH  0
#define Q_AL  10240
#define Q_BH  20480
#define Q_BL  30720
#define Q_STAGE 40960
#define Q_SMEM  81920

__global__ __launch_bounds__(256, 1) void qkv_mma()
{
    extern __shared__ char qsm[];

    const int tid  = threadIdx.x;
    const int wid  = tid >> 5;
    const int lane = tid & 31;
    const int g    = lane >> 2;
    const int tg   = lane & 3;
    const int lr   = lane & 7;

    const int warpM = (wid & 1) * 64;
    const int warpN = (wid >> 1) * 32;

    const int bm  = blockIdx.x * 128;
    const int bn  = blockIdx.y * 128;
    const int mat = blockIdx.z;

    const __nv_bfloat16* Wh = g_Wh + (size_t)mat * DIMN * DIMN;
    const __nv_bfloat16* Wl = g_Wl + (size_t)mat * DIMN * DIMN;
    __nv_bfloat16 *Yh, *Yl;
    if (mat == 0)      { Yh = g_Qh; Yl = g_Ql; }
    else if (mat == 1) { Yh = g_Kh; Yl = g_Kl; }
    else               { Yh = g_Vh; Yl = g_Vl; }

    const int prow = lane & 15;
    const int pcol = (lane >> 4) << 3;
    const int kko  = lr + ((lane >> 4) << 3);
    const int dof  = ((lane >> 3) & 1) << 3;

    float acc[4][4][4];
#pragma unroll
    for (int i = 0; i < 4; i++)
#pragma unroll
        for (int j = 0; j < 4; j++)
#pragma unroll
            for (int r = 0; r < 4; r++) acc[i][j][r] = 0.0f;

    auto load_stage = [&](int stage, int k0) {
        uint32_t base = smem_u32(qsm) + stage * Q_STAGE;
#pragma unroll
        for (int i = 0; i < 2; i++) {
            int s  = tid + 256 * i;
            int r  = s >> 2;
            int cc = (s & 3) * 8;
            uint32_t off = (uint32_t)(r * 80 + (s & 3) * 16);
            const size_t ga = (size_t)(bm + r) * DIMN + k0 + cc;
            cp16(base + Q_AH + off, g_Xh + ga);
            cp16(base + Q_AL + off, g_Xl + ga);
            const size_t gb = (size_t)(bn + r) * DIMN + k0 + cc;
            cp16(base + Q_BH + off, Wh + gb);
            cp16(base + Q_BL + off, Wl + gb);
        }
    };

    load_stage(0, 0);  cp_commit();
    load_stage(1, 32); cp_commit();

    const int NSTEP = DIMN / 32;   // 24
#pragma unroll 1
    for (int step = 0; step < NSTEP; step++) {
        cp_wait<1>();
        __syncthreads();

        uint32_t base = smem_u32(qsm) + (step & 1) * Q_STAGE;
#pragma unroll
        for (int c = 0; c < 2; c++) {
            uint32_t ah[4][4], al[4][4];
#pragma unroll
            for (int i = 0; i < 4; i++) {
                uint32_t ao = base + Q_AH +
                    (uint32_t)((warpM + 16 * i + prow) * 80 + c * 32 + pcol * 2);
                ldm_x4(ah[i], ao);
                ldm_x4(al[i], ao + (Q_AL - Q_AH));
            }
            uint32_t bh[2][4], bl[2][4];
#pragma unroll
            for (int p = 0; p < 2; p++) {
                uint32_t bo = base + Q_BH +
                    (uint32_t)((warpN + 16 * p + kko) * 80 + c * 32 + dof * 2);
                ldm_x4(bh[p], bo);
                ldm_x4(bl[p], bo + (Q_BL - Q_BH));
            }
#pragma unroll
            for (int i = 0; i < 4; i++)
#pragma unroll
                for (int p = 0; p < 2; p++) {
                    mma_bf16(acc[i][2 * p],     ah[i], bh[p][0], bh[p][1]);
                    mma_bf16(acc[i][2 * p],     al[i], bh[p][0], bh[p][1]);
                    mma_bf16(acc[i][2 * p],     ah[i], bl[p][0], bl[p][1]);
                    mma_bf16(acc[i][2 * p + 1], ah[i], bh[p][2], bh[p][3]);
                    mma_bf16(acc[i][2 * p + 1], al[i], bh[p][2], bh[p][3]);
                    mma_bf16(acc[i][2 * p + 1], ah[i], bl[p][2], bl[p][3]);
                }
        }
        __syncthreads();
        if (step + 2 < NSTEP) {
            load_stage(step & 1, (step + 2) * 32);
        }
        cp_commit();
    }

#pragma unroll
    for (int i = 0; i < 4; i++) {
        int row0 = bm + warpM + 16 * i + g;
#pragma unroll
        for (int j = 0; j < 4; j++) {
            int col = bn + warpN + 8 * j + 2 * tg;
            float c0 = acc[i][j][0], c1 = acc[i][j][1];
            float c2 = acc[i][j][2], c3 = acc[i][j][3];
            uint32_t h01 = packbf(c0, c1);
            uint32_t h23 = packbf(c2, c3);
            __nv_bfloat162 b01 = *(__nv_bfloat162*)&h01;
            __nv_bfloat162 b23 = *(__nv_bfloat162*)&h23;
            uint32_t l01 = packbf(c0 - __bfloat162float(b01.x),
                                  c1 - __bfloat162float(b01.y));
            uint32_t l23 = packbf(c2 - __bfloat162float(b23.x),
                                  c3 - __bfloat162float(b23.y));
            *(uint32_t*)(Yh + (size_t)row0 * DIMN + col)       = h01;
            *(uint32_t*)(Yh + (size_t)(row0 + 8) * DIMN + col) = h23;
            *(uint32_t*)(Yl + (size_t)row0 * DIMN + col)       = l01;
            *(uint32_t*)(Yl + (size_t)(row0 + 8) * DIMN + col) = l23;
        }
    }
}

// ---------------------------------------------------------------------------
// Kernel 2: fused attention. R12: identical math/layout to R11 (rel_err-
// preserving), but the softmax-exchange phase is decoupled per q-half with
// named barriers (bar.sync 1/2, 384). Only 3 CTA-wide barriers remain per
// tile (K-free / V-visible / V-free). The two halves are computationally
// independent: den for q row needs only the 12 heads of that row, all
// written by the same half's warps.
// ---------------------------------------------------------------------------
__global__ __launch_bounds__(768, 1) void attn_kernel(float* __restrict__ Out)
{
    extern __shared__ char sm[];
    __nv_bfloat16* sKh = (__nv_bfloat16*)(sm + OFF_A);
    __nv_bfloat16* sKl = (__nv_bfloat16*)(sm + OFF_A + A_LO);
    __nv_bfloat16* sVh = (__nv_bfloat16*)(sm + OFF_B);
    __nv_bfloat16* sVl = (__nv_bfloat16*)(sm + OFF_B + B_LO);
    float*         sP  = (float*)(sm + OFF_P);   // [NH][32][PST]
    float*         sI  = (float*)(sm + OFF_I);   // [2][32][PST]

    const int tid  = threadIdx.x;
    const int wid  = tid >> 5;
    const int lane = tid & 31;
    const int head = wid >> 1;
    const int qh   = wid & 1;
    const int g    = lane >> 2;
    const int tg   = lane & 3;
    const int lr   = lane & 7;

    // index of this thread within its 384-thread half (0..383)
    const int ht   = ((wid >> 1) << 5) | lane;
    const int barid = 1 + qh;

    const int b  = blockIdx.y;
    const int q0 = blockIdx.x * TQ;

    const float SCALE = 0.03608439182435161f;   // 1/sqrt(768)

    uint32_t qfh[4][4], qfl[4][4];
    {
        const int qrow = (b * SEQ + q0 + qh * 16 + g) * DIMN + head * HD;
#pragma unroll
        for (int c = 0; c < 4; c++) {
            int c0 = 2 * tg + 16 * c;
            qfh[c][0] = *(const uint32_t*)(g_Qh + qrow + c0);
            qfh[c][1] = *(const uint32_t*)(g_Qh + qrow + 8 * DIMN + c0);
            qfh[c][2] = *(const uint32_t*)(g_Qh + qrow + c0 + 8);
            qfh[c][3] = *(const uint32_t*)(g_Qh + qrow + 8 * DIMN + c0 + 8);
            qfl[c][0] = *(const uint32_t*)(g_Ql + qrow + c0);
            qfl[c][1] = *(const uint32_t*)(g_Ql + qrow + 8 * DIMN + c0);
            qfl[c][2] = *(const uint32_t*)(g_Ql + qrow + c0 + 8);
            qfl[c][3] = *(const uint32_t*)(g_Ql + qrow + 8 * DIMN + c0 + 8);
        }
    }

    float o[8][4];
#pragma unroll
    for (int j = 0; j < 8; j++)
#pragma unroll
        for (int r = 0; r < 4; r++) o[j][r] = 0.0f;

    const int kko_k = lr + ((lane >> 4) << 3);
    const int dof_k = ((lane >> 3) & 1) << 3;
    const int kko_v = lr + (((lane >> 3) & 1) << 3);
    const int dof_v = (lane >> 4) << 3;

    const size_t kvbase = (size_t)b * SEQ * DIMN;

    auto load_tile = [&](__nv_bfloat16* dh, __nv_bfloat16* dl,
                         const __nv_bfloat16* gh, const __nv_bfloat16* gl,
                         int kt) {
        const size_t gb = kvbase + (size_t)kt * DIMN;
#pragma unroll
        for (int i = 0; i < 4; i++) {
            int s  = tid + 768 * i;
            int r  = s / 96;
            int cc = (s % 96) * 8;
            cp16(smem_u32(dh + r * KSTR + cc), gh + gb + (size_t)r * DIMN + cc);
            cp16(smem_u32(dl + r * KSTR + cc), gl + gb + (size_t)r * DIMN + cc);
        }
    };

    // prologue: K(0), V(0) in flight; K(0) landed + visible
    load_tile(sKh, sKl, g_Kh, g_Kl, 0); cp_commit();
    load_tile(sVh, sVl, g_Vh, g_Vl, 0); cp_commit();
    cp_wait<1>();
    __syncthreads();

    float* Pq = sP + (head * 32 + qh * 16) * PST;
    // den assignment: this half's 256 active threads cover its 16 q rows
    const int dq = qh * 16 + (ht >> 4);   // global q row for den
    const int dk = ht & 15;               // k within round
    const bool den_active = (ht < 256);

    float s4[4][4];

#pragma unroll 1
    for (int kt = 0; kt < SEQ; kt += TK) {
        const bool has_next = (kt + TK) < SEQ;

        // ---- scores from K buffer (3-pass split bf16) ----
#pragma unroll
        for (int j = 0; j < 4; j++)
#pragma unroll
            for (int r = 0; r < 4; r++) s4[j][r] = 0.0f;

#pragma unroll
        for (int p = 0; p < 2; p++) {
#pragma unroll
            for (int c = 0; c < 4; c++) {
                int e = (16 * p + kko_k) * KSTR + head * HD + 16 * c + dof_k;
                uint32_t kh[4], kl[4];
                ldm_x4(kh, smem_u32(sKh + e));
                ldm_x4(kl, smem_u32(sKl + e));
                mma_bf16(s4[2 * p],     qfh[c], kh[0], kh[1]);
                mma_bf16(s4[2 * p],     qfl[c], kh[0], kh[1]);
                mma_bf16(s4[2 * p],     qfh[c], kl[0], kl[1]);
                mma_bf16(s4[2 * p + 1], qfh[c], kh[2], kh[3]);
                mma_bf16(s4[2 * p + 1], qfl[c], kh[2], kh[3]);
                mma_bf16(s4[2 * p + 1], qfh[c], kl[2], kl[3]);
            }
        }

        // ---- exp (MUFU) ----
#pragma unroll
        for (int j = 0; j < 4; j++)
#pragma unroll
            for (int r = 0; r < 4; r++) s4[j][r] = fast_exp(s4[j][r]);

        __syncthreads();                       // A: all K reads done -> K free
        if (has_next) { load_tile(sKh, sKl, g_Kh, g_Kl, kt + TK); cp_commit(); }

        // ==== decoupled per-half softmax exchange (named barriers) ====
        // round 0 (k 0..15)
#pragma unroll
        for (int j = 0; j < 2; j++) {
            *(float2*)(Pq + g * PST + 8 * j + 2 * tg)       = make_float2(s4[j][0], s4[j][1]);
            *(float2*)(Pq + (g + 8) * PST + 8 * j + 2 * tg) = make_float2(s4[j][2], s4[j][3]);
        }
        bar_half(barid);
        if (den_active) {
            float den = 0.0f;
#pragma unroll
            for (int h = 0; h < NH; h++) den += sP[(h * 32 + dq) * PST + dk];
            sI[dq * PST + dk] = __fdividef(SCALE, den);
        }
        bar_half(barid);
        // round 1 (k 16..31)
#pragma unroll
        for (int j = 2; j < 4; j++) {
            *(float2*)(Pq + g * PST + 8 * (j - 2) + 2 * tg)       = make_float2(s4[j][0], s4[j][1]);
            *(float2*)(Pq + (g + 8) * PST + 8 * (j - 2) + 2 * tg) = make_float2(s4[j][2], s4[j][3]);
        }
        bar_half(barid);
        if (den_active) {
            float den = 0.0f;
#pragma unroll
            for (int h = 0; h < NH; h++) den += sP[(h * 32 + dq) * PST + dk];
            sI[32 * PST + dq * PST + dk] = __fdividef(SCALE, den);
        }
        // ==== end decoupled phase ====

        if (has_next) cp_wait<1>(); else cp_wait<0>();   // V(t) landed
        __syncthreads();                       // B: V visible + sI complete (both halves)

        // ---- build P A-frags (hi + lo) from fp32 registers ----
        uint32_t ph[2][4], pl[2][4];
        {
            const int qr = qh * 16 + g;
#pragma unroll
            for (int c = 0; c < 2; c++) {
                const float* invh = sI + c * (32 * PST);
#pragma unroll
                for (int hf = 0; hf < 2; hf++) {
                    const float* ir = invh + (qr + 8 * hf) * PST + 2 * tg;
                    float2 iv0 = *(const float2*)(ir);
                    float2 iv1 = *(const float2*)(ir + 8);
                    float p0 = s4[2 * c][2 * hf]     * iv0.x;
                    float p1 = s4[2 * c][2 * hf + 1] * iv0.y;
                    float p2 = s4[2 * c + 1][2 * hf]     * iv1.x;
                    float p3 = s4[2 * c + 1][2 * hf + 1] * iv1.y;
                    uint32_t h0 = packbf(p0, p1);
                    uint32_t h1 = packbf(p2, p3);
                    __nv_bfloat162 b0 = *(__nv_bfloat162*)&h0;
                    __nv_bfloat162 b1 = *(__nv_bfloat162*)&h1;
                    ph[c][hf]     = h0;
                    ph[c][2 + hf] = h1;
                    pl[c][hf]     = packbf(p0 - __bfloat162float(b0.x),
                                           p1 - __bfloat162float(b0.y));
                    pl[c][2 + hf] = packbf(p2 - __bfloat162float(b1.x),
                                           p3 - __bfloat162float(b1.y));
                }
            }
        }

        // ---- AV (3-pass: Ph Vh + Pl Vh + Ph Vl) ----
#pragma unroll
        for (int c = 0; c < 2; c++) {
#pragma unroll
            for (int dp = 0; dp < 4; dp++) {
                int e = (16 * c + kko_v) * KSTR + head * HD + 16 * dp + dof_v;
                uint32_t vh[4], vl[4];
                ldm_x4_t(vh, smem_u32(sVh + e));
                ldm_x4_t(vl, smem_u32(sVl + e));
                mma_bf16(o[2 * dp],     ph[c], vh[0], vh[1]);
                mma_bf16(o[2 * dp],     pl[c], vh[0], vh[1]);
                mma_bf16(o[2 * dp],     ph[c], vl[0], vl[1]);
                mma_bf16(o[2 * dp + 1], ph[c], vh[2], vh[3]);
                mma_bf16(o[2 * dp + 1], pl[c], vh[2], vh[3]);
                mma_bf16(o[2 * dp + 1], ph[c], vl[2], vl[3]);
            }
        }

        cp_wait<0>();                          // K(t+1) landed
        __syncthreads();                       // C: AV done -> V free; K(t+1) visible
        if (has_next) { load_tile(sVh, sVl, g_Vh, g_Vl, kt + TK); cp_commit(); }
    }

    // ---- writeout ----
    float* Ob = Out + (size_t)(b * SEQ + q0 + qh * 16) * DIMN + head * HD;
#pragma unroll
    for (int j = 0; j < 8; j++) {
        int d = 8 * j + 2 * tg;
        *(float2*)(Ob + (size_t)g * DIMN + d)       = make_float2(o[j][0], o[j][1]);
        *(float2*)(Ob + (size_t)(g + 8) * DIMN + d) = make_float2(o[j][2], o[j][3]);
    }
}

// ---------------------------------------------------------------------------
extern "C" void kernel_launch(void* const* d_in, const int* in_sizes, int n_in,
                              void* d_out, int out_size)
{
    const float* x  = (const float*)d_in[0];
    const float* Wq = (const float*)d_in[1];
    const float* Wk = (const float*)d_in[2];
    const float* Wv = (const float*)d_in[3];
    float* out = (float*)d_out;

    {
        int n4x = 4096 * DIMN / 4;
        cvt_split<<<(n4x + 255) / 256, 256>>>(x, 0, 0, n4x);
        int n4w = DIMN * DIMN / 4;
        cvt_split<<<(n4w + 255) / 256, 256>>>(Wq, 1, 0, n4w);
        cvt_split<<<(n4w + 255) / 256, 256>>>(Wk, 1, DIMN * DIMN, n4w);
        cvt_split<<<(n4w + 255) / 256, 256>>>(Wv, 1, 2 * DIMN * DIMN, n4w);
    }

    cudaFuncSetAttribute(qkv_mma, cudaFuncAttributeMaxDynamicSharedMemorySize, Q_SMEM);
    dim3 g1(4096 / 128, DIMN / 128, 3);
    qkv_mma<<<g1, 256, Q_SMEM>>>();

    cudaFuncSetAttribute(attn_kernel, cudaFuncAttributeMaxDynamicSharedMemorySize, SMEM_TOTAL);
    dim3 g2(SEQ / TQ, BATCH);
    attn_kernel<<<g2, 768, SMEM_TOTAL>>>(out);
}

// round 14
// speedup vs baseline: 1.0562x; 1.0562x over previous
#include <cuda_runtime.h>
#include <cuda_bf16.h>
#include <cstdint>

#define BATCH 2
#define SEQ   2048
#define DIMN  768
#define NH    12
#define HD    64

#define TQ 32
#define TK 32

#define KSTR 776           /* bf16 row stride: 1552B -> 16B aligned, conflict-free ldmatrix */
#define PST  18            /* fp32 exp-exchange row stride (floats); even -> float2-aligned */

// attn smem layout (bytes)
#define OFF_A   0                         /* K tile: hi, then lo            */
#define A_LO    49664                     /* 32*776*2                        */
#define OFF_B   99328                     /* V tile: hi, then lo             */
#define B_LO    49664
#define OFF_P   198656                    /* sP fp32 [NH][32][PST] = 27648   */
#define OFF_I   226304                    /* sInv fp32 [2][32][PST] = 4608   */
#define SMEM_TOTAL 230912

// split-bf16 operands
__device__ __align__(16) __nv_bfloat16 g_Xh[4096 * DIMN];
__device__ __align__(16) __nv_bfloat16 g_Xl[4096 * DIMN];
__device__ __align__(16) __nv_bfloat16 g_Wh[3 * DIMN * DIMN];
__device__ __align__(16) __nv_bfloat16 g_Wl[3 * DIMN * DIMN];

// split-bf16 Q/K/V (hi + lo)
__device__ __align__(16) __nv_bfloat16 g_Qh[BATCH * SEQ * DIMN];
__device__ __align__(16) __nv_bfloat16 g_Ql[BATCH * SEQ * DIMN];
__device__ __align__(16) __nv_bfloat16 g_Kh[BATCH * SEQ * DIMN];
__device__ __align__(16) __nv_bfloat16 g_Kl[BATCH * SEQ * DIMN];
__device__ __align__(16) __nv_bfloat16 g_Vh[BATCH * SEQ * DIMN];
__device__ __align__(16) __nv_bfloat16 g_Vl[BATCH * SEQ * DIMN];

// ---------------------------------------------------------------------------
// exp via MUFU (EX2); tensor cores own the math, MUFU pipe is idle.
__device__ __forceinline__ float fast_exp(float s) {
    float t = s * 1.4426950408889634f;
    float r;
    asm("ex2.approx.f32 %0, %1;" : "=f"(r) : "f"(t));
    return r;
}

__device__ __forceinline__ uint32_t smem_u32(const void* p) {
    return (uint32_t)__cvta_generic_to_shared(p);
}
__device__ __forceinline__ void ldm_x4(uint32_t r[4], uint32_t addr) {
    asm volatile("ldmatrix.sync.aligned.m8n8.x4.shared.b16 {%0,%1,%2,%3}, [%4];"
                 : "=r"(r[0]), "=r"(r[1]), "=r"(r[2]), "=r"(r[3]) : "r"(addr));
}
__device__ __forceinline__ void ldm_x4_t(uint32_t r[4], uint32_t addr) {
    asm volatile("ldmatrix.sync.aligned.m8n8.x4.trans.shared.b16 {%0,%1,%2,%3}, [%4];"
                 : "=r"(r[0]), "=r"(r[1]), "=r"(r[2]), "=r"(r[3]) : "r"(addr));
}
__device__ __forceinline__ void mma_bf16(float c[4], const uint32_t a[4],
                                         uint32_t b0, uint32_t b1) {
    asm volatile(
        "mma.sync.aligned.m16n8k16.row.col.f32.bf16.bf16.f32 "
        "{%0,%1,%2,%3}, {%4,%5,%6,%7}, {%8,%9}, {%0,%1,%2,%3};"
        : "+f"(c[0]), "+f"(c[1]), "+f"(c[2]), "+f"(c[3])
        : "r"(a[0]), "r"(a[1]), "r"(a[2]), "r"(a[3]), "r"(b0), "r"(b1));
}
__device__ __forceinline__ void cp16(uint32_t saddr, const void* gaddr) {
    asm volatile("cp.async.cg.shared.global [%0], [%1], 16;"
                 :: "r"(saddr), "l"(gaddr));
}
__device__ __forceinline__ void cp_commit() {
    asm volatile("cp.async.commit_group;" ::: "memory");
}
template <int N>
__device__ __forceinline__ void cp_wait() {
    asm volatile("cp.async.wait_group %0;" :: "n"(N) : "memory");
}
__device__ __forceinline__ uint32_t packbf(float a, float b) {
    __nv_bfloat162 h = __floats2bfloat162_rn(a, b);   // .x=a -> low half
    return *(uint32_t*)&h;
}

// ---------------------------------------------------------------------------
// Kernel 0: fp32 -> split bf16 (hi, lo), ALL inputs in ONE launch.
// Block mapping: bid < NBX -> X; else W segment (bid-NBX)/NBW in {0,1,2}.
// Destinations resolved in device code (never pass __device__ globals as
// kernel args from host).
// ---------------------------------------------------------------------------
#define CVT_N4X (4096 * DIMN / 4)          /* 786432 */
#define CVT_N4W (DIMN * DIMN / 4)          /* 147456 */
#define CVT_NBX ((CVT_N4X + 255) / 256)    /* 3072   */
#define CVT_NBW ((CVT_N4W + 255) / 256)    /* 576    */
#define CVT_NB  (CVT_NBX + 3 * CVT_NBW)    /* 4800   */

__global__ __launch_bounds__(256) void cvt_split_all(
    const float* __restrict__ x,
    const float* __restrict__ wq,
    const float* __restrict__ wk,
    const float* __restrict__ wv)
{
    int bid = blockIdx.x;
    const float* src;
    __nv_bfloat16 *dh, *dl;
    int i;
    if (bid < CVT_NBX) {
        i = bid * 256 + threadIdx.x;
        if (i >= CVT_N4X) return;
        src = x; dh = g_Xh; dl = g_Xl;
    } else {
        int seg = (bid - CVT_NBX) / CVT_NBW;          // 0,1,2
        int sb  = (bid - CVT_NBX) - seg * CVT_NBW;
        i = sb * 256 + threadIdx.x;
        if (i >= CVT_N4W) return;
        src = (seg == 0) ? wq : (seg == 1) ? wk : wv;
        dh = g_Wh + (size_t)seg * DIMN * DIMN;
        dl = g_Wl + (size_t)seg * DIMN * DIMN;
    }

    float4 v = ((const float4*)src)[i];
    __nv_bfloat162 h0 = __floats2bfloat162_rn(v.x, v.y);
    __nv_bfloat162 h1 = __floats2bfloat162_rn(v.z, v.w);
    __nv_bfloat162 l0 = __floats2bfloat162_rn(v.x - __bfloat162float(h0.x),
                                              v.y - __bfloat162float(h0.y));
    __nv_bfloat162 l1 = __floats2bfloat162_rn(v.z - __bfloat162float(h1.x),
                                              v.w - __bfloat162float(h1.y));
    ((__nv_bfloat162*)dh)[2 * i]     = h0;
    ((__nv_bfloat162*)dh)[2 * i + 1] = h1;
    ((__nv_bfloat162*)dl)[2 * i]     = l0;
    ((__nv_bfloat162*)dl)[2 * i + 1] = l1;
}

// ---------------------------------------------------------------------------
// Kernel 1: QKV projection on tensor cores, split-bf16 3-pass.
// R13: __launch_bounds__(256, 2) -> 2 CTAs/SM (smem 80KB x2 = 160KB fits);
// cross-CTA latency hiding of cp_wait/barriers. Math unchanged.
// ---------------------------------------------------------------------------
#define Q_AH  0
#define Q_AL  10240
#define Q_BH  20480
#define Q_BL  30720
#define Q_STAGE 40960
#define Q_SMEM  81920

__global__ __launch_bounds__(256, 2) void qkv_mma()
{
    extern __shared__ char qsm[];

    const int tid  = threadIdx.x;
    const int wid  = tid >> 5;
    const int lane = tid & 31;
    const int g    = lane >> 2;
    const int tg   = lane & 3;
    const int lr   = lane & 7;

    const int warpM = (wid & 1) * 64;
    const int warpN = (wid >> 1) * 32;

    const int bm  = blockIdx.x * 128;
    const int bn  = blockIdx.y * 128;
    const int mat = blockIdx.z;

    const __nv_bfloat16* Wh = g_Wh + (size_t)mat * DIMN * DIMN;
    const __nv_bfloat16* Wl = g_Wl + (size_t)mat * DIMN * DIMN;
    __nv_bfloat16 *Yh, *Yl;
    if (mat == 0)      { Yh = g_Qh; Yl = g_Ql; }
    else if (mat == 1) { Yh = g_Kh; Yl = g_Kl; }
    else               { Yh = g_Vh; Yl = g_Vl; }

    const int prow = lane & 15;
    const int pcol = (lane >> 4) << 3;
    const int kko  = lr + ((lane >> 4) << 3);
    const int dof  = ((lane >> 3) & 1) << 3;

    float acc[4][4][4];
#pragma unroll
    for (int i = 0; i < 4; i++)
#pragma unroll
        for (int j = 0; j < 4; j++)
#pragma unroll
            for (int r = 0; r < 4; r++) acc[i][j][r] = 0.0f;

    auto load_stage = [&](int stage, int k0) {
        uint32_t base = smem_u32(qsm) + stage * Q_STAGE;
#pragma unroll
        for (int i = 0; i < 2; i++) {
            int s  = tid + 256 * i;
            int r  = s >> 2;
            int cc = (s & 3) * 8;
            uint32_t off = (uint32_t)(r * 80 + (s & 3) * 16);
            const size_t ga = (size_t)(bm + r) * DIMN + k0 + cc;
            cp16(base + Q_AH + off, g_Xh + ga);
            cp16(base + Q_AL + off, g_Xl + ga);
            const size_t gb = (size_t)(bn + r) * DIMN + k0 + cc;
            cp16(base + Q_BH + off, Wh + gb);
            cp16(base + Q_BL + off, Wl + gb);
        }
    };

    load_stage(0, 0);  cp_commit();
    load_stage(1, 32); cp_commit();

    const int NSTEP = DIMN / 32;   // 24
#pragma unroll 1
    for (int step = 0; step < NSTEP; step++) {
        cp_wait<1>();
        __syncthreads();

        uint32_t base = smem_u32(qsm) + (step & 1) * Q_STAGE;
#pragma unroll
        for (int c = 0; c < 2; c++) {
            uint32_t ah[4][4], al[4][4];
#pragma unroll
            for (int i = 0; i < 4; i++) {
                uint32_t ao = base + Q_AH +
                    (uint32_t)((warpM + 16 * i + prow) * 80 + c * 32 + pcol * 2);
                ldm_x4(ah[i], ao);
                ldm_x4(al[i], ao + (Q_AL - Q_AH));
            }
            uint32_t bh[2][4], bl[2][4];
#pragma unroll
            for (int p = 0; p < 2; p++) {
                uint32_t bo = base + Q_BH +
                    (uint32_t)((warpN + 16 * p + kko) * 80 + c * 32 + dof * 2);
                ldm_x4(bh[p], bo);
                ldm_x4(bl[p], bo + (Q_BL - Q_BH));
            }
#pragma unroll
            for (int i = 0; i < 4; i++)
#pragma unroll
                for (int p = 0; p < 2; p++) {
                    mma_bf16(acc[i][2 * p],     ah[i], bh[p][0], bh[p][1]);
                    mma_bf16(acc[i][2 * p],     al[i], bh[p][0], bh[p][1]);
                    mma_bf16(acc[i][2 * p],     ah[i], bl[p][0], bl[p][1]);
                    mma_bf16(acc[i][2 * p + 1], ah[i], bh[p][2], bh[p][3]);
                    mma_bf16(acc[i][2 * p + 1], al[i], bh[p][2], bh[p][3]);
                    mma_bf16(acc[i][2 * p + 1], ah[i], bl[p][2], bl[p][3]);
                }
        }
        __syncthreads();
        if (step + 2 < NSTEP) {
            load_stage(step & 1, (step + 2) * 32);
        }
        cp_commit();
    }

#pragma unroll
    for (int i = 0; i < 4; i++) {
        int row0 = bm + warpM + 16 * i + g;
#pragma unroll
        for (int j = 0; j < 4; j++) {
            int col = bn + warpN + 8 * j + 2 * tg;
            float c0 = acc[i][j][0], c1 = acc[i][j][1];
            float c2 = acc[i][j][2], c3 = acc[i][j][3];
            uint32_t h01 = packbf(c0, c1);
            uint32_t h23 = packbf(c2, c3);
            __nv_bfloat162 b01 = *(__nv_bfloat162*)&h01;
            __nv_bfloat162 b23 = *(__nv_bfloat162*)&h23;
            uint32_t l01 = packbf(c0 - __bfloat162float(b01.x),
                                  c1 - __bfloat162float(b01.y));
            uint32_t l23 = packbf(c2 - __bfloat162float(b23.x),
                                  c3 - __bfloat162float(b23.y));
            *(uint32_t*)(Yh + (size_t)row0 * DIMN + col)       = h01;
            *(uint32_t*)(Yh + (size_t)(row0 + 8) * DIMN + col) = h23;
            *(uint32_t*)(Yl + (size_t)row0 * DIMN + col)       = l01;
            *(uint32_t*)(Yl + (size_t)(row0 + 8) * DIMN + col) = l23;
        }
    }
}

// ---------------------------------------------------------------------------
// Kernel 2: fused attention — R11 passing version VERBATIM (best: 659.5us).
// fp32 two-round half-width exchange, 3-pass scores + 3-pass AV, MUFU exp,
// cp.async prefetch with disjoint buffer lifetimes, 5 CTA barriers/tile.
// ---------------------------------------------------------------------------
__global__ __launch_bounds__(768, 1) void attn_kernel(float* __restrict__ Out)
{
    extern __shared__ char sm[];
    __nv_bfloat16* sKh = (__nv_bfloat16*)(sm + OFF_A);
    __nv_bfloat16* sKl = (__nv_bfloat16*)(sm + OFF_A + A_LO);
    __nv_bfloat16* sVh = (__nv_bfloat16*)(sm + OFF_B);
    __nv_bfloat16* sVl = (__nv_bfloat16*)(sm + OFF_B + B_LO);
    float*         sP  = (float*)(sm + OFF_P);
    float*         sI  = (float*)(sm + OFF_I);

    const int tid  = threadIdx.x;
    const int wid  = tid >> 5;
    const int lane = tid & 31;
    const int head = wid >> 1;
    const int qh   = wid & 1;
    const int g    = lane >> 2;
    const int tg   = lane & 3;
    const int lr   = lane & 7;

    const int b  = blockIdx.y;
    const int q0 = blockIdx.x * TQ;

    const float SCALE = 0.03608439182435161f;   // 1/sqrt(768)

    uint32_t qfh[4][4], qfl[4][4];
    {
        const int qrow = (b * SEQ + q0 + qh * 16 + g) * DIMN + head * HD;
#pragma unroll
        for (int c = 0; c < 4; c++) {
            int c0 = 2 * tg + 16 * c;
            qfh[c][0] = *(const uint32_t*)(g_Qh + qrow + c0);
            qfh[c][1] = *(const uint32_t*)(g_Qh + qrow + 8 * DIMN + c0);
            qfh[c][2] = *(const uint32_t*)(g_Qh + qrow + c0 + 8);
            qfh[c][3] = *(const uint32_t*)(g_Qh + qrow + 8 * DIMN + c0 + 8);
            qfl[c][0] = *(const uint32_t*)(g_Ql + qrow + c0);
            qfl[c][1] = *(const uint32_t*)(g_Ql + qrow + 8 * DIMN + c0);
            qfl[c][2] = *(const uint32_t*)(g_Ql + qrow + c0 + 8);
            qfl[c][3] = *(const uint32_t*)(g_Ql + qrow + 8 * DIMN + c0 + 8);
        }
    }

    float o[8][4];
#pragma unroll
    for (int j = 0; j < 8; j++)
#pragma unroll
        for (int r = 0; r < 4; r++) o[j][r] = 0.0f;

    const int kko_k = lr + ((lane >> 4) << 3);
    const int dof_k = ((lane >> 3) & 1) << 3;
    const int kko_v = lr + (((lane >> 3) & 1) << 3);
    const int dof_v = (lane >> 4) << 3;

    const size_t kvbase = (size_t)b * SEQ * DIMN;

    auto load_tile = [&](__nv_bfloat16* dh, __nv_bfloat16* dl,
                         const __nv_bfloat16* gh, const __nv_bfloat16* gl,
                         int kt) {
        const size_t gb = kvbase + (size_t)kt * DIMN;
#pragma unroll
        for (int i = 0; i < 4; i++) {
            int s  = tid + 768 * i;
            int r  = s / 96;
            int cc = (s % 96) * 8;
            cp16(smem_u32(dh + r * KSTR + cc), gh + gb + (size_t)r * DIMN + cc);
            cp16(smem_u32(dl + r * KSTR + cc), gl + gb + (size_t)r * DIMN + cc);
        }
    };

    load_tile(sKh, sKl, g_Kh, g_Kl, 0); cp_commit();
    load_tile(sVh, sVl, g_Vh, g_Vl, 0); cp_commit();
    cp_wait<1>();
    __syncthreads();

    float* Pq = sP + (head * 32 + qh * 16) * PST;
    float s4[4][4];

#pragma unroll 1
    for (int kt = 0; kt < SEQ; kt += TK) {
        const bool has_next = (kt + TK) < SEQ;

#pragma unroll
        for (int j = 0; j < 4; j++)
#pragma unroll
            for (int r = 0; r < 4; r++) s4[j][r] = 0.0f;

#pragma unroll
        for (int p = 0; p < 2; p++) {
#pragma unroll
            for (int c = 0; c < 4; c++) {
                int e = (16 * p + kko_k) * KSTR + head * HD + 16 * c + dof_k;
                uint32_t kh[4], kl[4];
                ldm_x4(kh, smem_u32(sKh + e));
                ldm_x4(kl, smem_u32(sKl + e));
                mma_bf16(s4[2 * p],     qfh[c], kh[0], kh[1]);
                mma_bf16(s4[2 * p],     qfl[c], kh[0], kh[1]);
                mma_bf16(s4[2 * p],     qfh[c], kl[0], kl[1]);
                mma_bf16(s4[2 * p + 1], qfh[c], kh[2], kh[3]);
                mma_bf16(s4[2 * p + 1], qfl[c], kh[2], kh[3]);
                mma_bf16(s4[2 * p + 1], qfh[c], kl[2], kl[3]);
            }
        }

#pragma unroll
        for (int j = 0; j < 4; j++)
#pragma unroll
            for (int r = 0; r < 4; r++) s4[j][r] = fast_exp(s4[j][r]);

#pragma unroll
        for (int j = 0; j < 2; j++) {
            *(float2*)(Pq + g * PST + 8 * j + 2 * tg)       = make_float2(s4[j][0], s4[j][1]);
            *(float2*)(Pq + (g + 8) * PST + 8 * j + 2 * tg) = make_float2(s4[j][2], s4[j][3]);
        }
        __syncthreads();
        if (has_next) load_tile(sKh, sKl, g_Kh, g_Kl, kt + TK);
        cp_commit();

        if (tid < 512) {
            int q = tid >> 4, k = tid & 15;
            float den = 0.0f;
#pragma unroll
            for (int h = 0; h < NH; h++) den += sP[(h * 32 + q) * PST + k];
            sI[q * PST + k] = __fdividef(SCALE, den);
        }
        __syncthreads();

#pragma unroll
        for (int j = 2; j < 4; j++) {
            *(float2*)(Pq + g * PST + 8 * (j - 2) + 2 * tg)       = make_float2(s4[j][0], s4[j][1]);
            *(float2*)(Pq + (g + 8) * PST + 8 * (j - 2) + 2 * tg) = make_float2(s4[j][2], s4[j][3]);
        }
        __syncthreads();

        if (tid < 512) {
            int q = tid >> 4, k = tid & 15;
            float den = 0.0f;
#pragma unroll
            for (int h = 0; h < NH; h++) den += sP[(h * 32 + q) * PST + k];
            sI[32 * PST + q * PST + k] = __fdividef(SCALE, den);
        }
        if (has_next) cp_wait<1>(); else cp_wait<0>();
        __syncthreads();

        uint32_t ph[2][4], pl[2][4];
        {
            const int qr = qh * 16 + g;
#pragma unroll
            for (int c = 0; c < 2; c++) {
                const float* invh = sI + c * (32 * PST);
#pragma unroll
                for (int hf = 0; hf < 2; hf++) {
                    const float* ir = invh + (qr + 8 * hf) * PST + 2 * tg;
                    float2 iv0 = *(const float2*)(ir);
                    float2 iv1 = *(const float2*)(ir + 8);
                    float p0 = s4[2 * c][2 * hf]     * iv0.x;
                    float p1 = s4[2 * c][2 * hf + 1] * iv0.y;
                    float p2 = s4[2 * c + 1][2 * hf]     * iv1.x;
                    float p3 = s4[2 * c + 1][2 * hf + 1] * iv1.y;
                    uint32_t h0 = packbf(p0, p1);
                    uint32_t h1 = packbf(p2, p3);
                    __nv_bfloat162 b0 = *(__nv_bfloat162*)&h0;
                    __nv_bfloat162 b1 = *(__nv_bfloat162*)&h1;
                    ph[c][hf]     = h0;
                    ph[c][2 + hf] = h1;
                    pl[c][hf]     = packbf(p0 - __bfloat162float(b0.x),
                                           p1 - __bfloat162float(b0.y));
                    pl[c][2 + hf] = packbf(p2 - __bfloat162float(b1.x),
                                           p3 - __bfloat162float(b1.y));
                }
            }
        }

#pragma unroll
        for (int c = 0; c < 2; c++) {
#pragma unroll
            for (int dp = 0; dp < 4; dp++) {
                int e = (16 * c + kko_v) * KSTR + head * HD + 16 * dp + dof_v;
                uint32_t vh[4], vl[4];
                ldm_x4_t(vh, smem_u32(sVh + e));
                ldm_x4_t(vl, smem_u32(sVl + e));
                mma_bf16(o[2 * dp],     ph[c], vh[0], vh[1]);
                mma_bf16(o[2 * dp],     pl[c], vh[0], vh[1]);
                mma_bf16(o[2 * dp],     ph[c], vl[0], vl[1]);
                mma_bf16(o[2 * dp + 1], ph[c], vh[2], vh[3]);
                mma_bf16(o[2 * dp + 1], pl[c], vh[2], vh[3]);
                mma_bf16(o[2 * dp + 1], ph[c], vl[2], vl[3]);
            }
        }

        cp_wait<0>();
        __syncthreads();
        if (has_next) load_tile(sVh, sVl, g_Vh, g_Vl, kt + TK);
        cp_commit();
    }

    float* Ob = Out + (size_t)(b * SEQ + q0 + qh * 16) * DIMN + head * HD;
#pragma unroll
    for (int j = 0; j < 8; j++) {
        int d = 8 * j + 2 * tg;
        *(float2*)(Ob + (size_t)g * DIMN + d)       = make_float2(o[j][0], o[j][1]);
        *(float2*)(Ob + (size_t)(g + 8) * DIMN + d) = make_float2(o[j][2], o[j][3]);
    }
}

// ---------------------------------------------------------------------------
extern "C" void kernel_launch(void* const* d_in, const int* in_sizes, int n_in,
                              void* d_out, int out_size)
{
    const float* x  = (const float*)d_in[0];
    const float* Wq = (const float*)d_in[1];
    const float* Wk = (const float*)d_in[2];
    const float* Wv = (const float*)d_in[3];
    float* out = (float*)d_out;

    // single fused convert launch (X + Wq + Wk + Wv)
    cvt_split_all<<<CVT_NB, 256>>>(x, Wq, Wk, Wv);

    cudaFuncSetAttribute(qkv_mma, cudaFuncAttributeMaxDynamicSharedMemorySize, Q_SMEM);
    dim3 g1(4096 / 128, DIMN / 128, 3);
    qkv_mma<<<g1, 256, Q_SMEM>>>();

    cudaFuncSetAttribute(attn_kernel, cudaFuncAttributeMaxDynamicSharedMemorySize, SMEM_TOTAL);
    dim3 g2(SEQ / TQ, BATCH);
    attn_kernel<<<g2, 768, SMEM_TOTAL>>>(out);
}